// round 7
// baseline (speedup 1.0000x reference)
#include <cuda_runtime.h>
#include <cuda_bf16.h>
#include <cstdint>

#define D 128
#define MAXN 65536
#define MAXE (1 << 20)
#define EPS 0.1f

// ======================= scratch (device globals) =======================
__device__ int          g_is64;
__device__ unsigned int g_or;
__device__ int   g_cnt[MAXN];
__device__ int   g_cursor[MAXN];
__device__ int   g_off[MAXN + 1];
__device__ int   g_csr[MAXE];
__device__ float g_coef[MAXE];
__device__ float g_al[MAXN];
__device__ float g_ar[MAXN];
__device__ float g_dinv[MAXN];
// bf16 split of aggregated features, row-major [MAXN][128] bf16 = 16 uint4/row
__device__ uint4 g_ahi[(size_t)MAXN * 16];
__device__ uint4 g_alo[(size_t)MAXN * 16];
// W^T split, row-major [n][k] bf16 (k contiguous), 16 uint4 per row
__device__ uint4 g_whi[2048];
__device__ uint4 g_wlo[2048];

__device__ __forceinline__ uint32_t smem_u32(const void* p) {
    uint32_t a;
    asm("{.reg .u64 t; cvta.to.shared.u64 t, %1; cvt.u32.u64 %0, t;}"
        : "=r"(a) : "l"(p));
    return a;
}
__device__ __forceinline__ uint32_t pack_bf16x2(float a, float b) {
    __nv_bfloat16 ha = __float2bfloat16(a), hb = __float2bfloat16(b);
    return ((uint32_t)*(uint16_t*)&hb << 16) | *(uint16_t*)&ha;
}
__device__ __forceinline__ float bf16_hi(float a) {
    return __bfloat162float(__float2bfloat16(a));
}

// ======================= preprocessing kernels =======================
__global__ void k_zero(int N) {
    int i = blockIdx.x * blockDim.x + threadIdx.x;
    if (i < N) { g_cnt[i] = 0; g_cursor[i] = 0; }
    if (i == 0) g_or = 0u;
}
// probe: OR odd int32 words of first Ep pairs (int64 -> all hi-words == 0)
__global__ void k_probe(const unsigned int* __restrict__ p, int Ep) {
    unsigned int v = 0;
    for (int i = blockIdx.x * blockDim.x + threadIdx.x; i < Ep;
         i += gridDim.x * blockDim.x)
        v |= p[2 * i + 1];
    #pragma unroll
    for (int o = 16; o > 0; o >>= 1) v |= __shfl_down_sync(0xFFFFFFFFu, v, o);
    if ((threadIdx.x & 31) == 0 && v) atomicOr(&g_or, v);
}
__global__ void k_setflag() { g_is64 = (g_or == 0u) ? 1 : 0; }

__device__ __forceinline__ int edge_src(const int* __restrict__ p, int E, int i) {
    return g_is64 ? p[2 * i] : p[i];
}
__device__ __forceinline__ int edge_dst(const int* __restrict__ p, int E, int i) {
    return g_is64 ? p[2 * (E + i)] : p[E + i];
}

__global__ void k_count(const int* __restrict__ p, int E) {
    int i = blockIdx.x * blockDim.x + threadIdx.x;
    if (i < E) atomicAdd(&g_cnt[edge_dst(p, E, i)], 1);
}

__global__ void k_node(const float4* __restrict__ x4,
                       const float4* __restrict__ attl4,
                       const float4* __restrict__ attr4, int N) {
    int warp = (blockIdx.x * blockDim.x + threadIdx.x) >> 5;
    int lane = threadIdx.x & 31;
    if (warp >= N) return;
    float4 xv = x4[(size_t)warp * 32 + lane];
    float4 lv = attl4[lane];
    float4 rv = attr4[lane];
    float pl = xv.x * lv.x + xv.y * lv.y + xv.z * lv.z + xv.w * lv.w;
    float pr = xv.x * rv.x + xv.y * rv.y + xv.z * rv.z + xv.w * rv.w;
    #pragma unroll
    for (int o = 16; o > 0; o >>= 1) {
        pl += __shfl_down_sync(0xFFFFFFFFu, pl, o);
        pr += __shfl_down_sync(0xFFFFFFFFu, pr, o);
    }
    if (lane == 0) {
        g_al[warp] = pl;
        g_ar[warp] = pr;
        g_dinv[warp] = rsqrtf((float)g_cnt[warp] + 1.0f);
    }
}

__global__ void k_scan(int N) {
    __shared__ int warp_sums[32];
    int t = threadIdx.x;
    int lane = t & 31, w = t >> 5;
    int chunk = (N + 1023) >> 10;
    int begin = t * chunk;
    int end = begin + chunk; if (end > N) end = N; if (begin > N) begin = N;
    int local = 0;
    for (int i = begin; i < end; i++) local += g_cnt[i];
    int v = local;
    #pragma unroll
    for (int o = 1; o < 32; o <<= 1) {
        int u = __shfl_up_sync(0xFFFFFFFFu, v, o);
        if (lane >= o) v += u;
    }
    if (lane == 31) warp_sums[w] = v;
    __syncthreads();
    if (w == 0) {
        int s = warp_sums[lane];
        #pragma unroll
        for (int o = 1; o < 32; o <<= 1) {
            int u = __shfl_up_sync(0xFFFFFFFFu, s, o);
            if (lane >= o) s += u;
        }
        warp_sums[lane] = s;
    }
    __syncthreads();
    int incl = v + (w > 0 ? warp_sums[w - 1] : 0);
    int run = incl - local;
    for (int i = begin; i < end; i++) { g_off[i] = run; run += g_cnt[i]; }
    if (t == 1023) g_off[N] = run;
}

// CSR build + per-edge coefficient (tanh once per edge)
__global__ void k_build(const int* __restrict__ p, int E) {
    int i = blockIdx.x * blockDim.x + threadIdx.x;
    if (i < E) {
        int r = edge_src(p, E, i);
        int c = edge_dst(p, E, i);
        int pos = g_off[c] + atomicAdd(&g_cursor[c], 1);
        g_csr[pos] = r;
        g_coef[pos] = tanhf(g_al[r] + g_ar[c]) * g_dinv[r] * g_dinv[c];
    }
}

// gather-aggregate (warp/node, register acc) -> bf16 hi/lo split output
__global__ void k_gather(const float4* __restrict__ x4, int N) {
    int n = (blockIdx.x * blockDim.x + threadIdx.x) >> 5;
    int lane = threadIdx.x & 31;
    if (n >= N) return;
    float dv  = g_dinv[n];
    float s = EPS + tanhf(g_al[n] + g_ar[n]) * dv * dv;   // self loop + eps
    float4 xv = x4[(size_t)n * 32 + lane];
    float4 acc = make_float4(xv.x * s, xv.y * s, xv.z * s, xv.w * s);
    int e   = g_off[n];
    int end = g_off[n + 1];
    for (; e < end; e++) {
        int r = g_csr[e];
        float coef = g_coef[e];
        float4 v = x4[(size_t)r * 32 + lane];
        acc.x += v.x * coef; acc.y += v.y * coef;
        acc.z += v.z * coef; acc.w += v.w * coef;
    }
    float hx = bf16_hi(acc.x), hy = bf16_hi(acc.y);
    float hz = bf16_hi(acc.z), hw = bf16_hi(acc.w);
    uint2 hi = make_uint2(pack_bf16x2(acc.x, acc.y), pack_bf16x2(acc.z, acc.w));
    uint2 lo = make_uint2(pack_bf16x2(acc.x - hx, acc.y - hy),
                          pack_bf16x2(acc.z - hz, acc.w - hw));
    ((uint2*)g_ahi)[(size_t)n * 32 + lane] = hi;
    ((uint2*)g_alo)[(size_t)n * 32 + lane] = lo;
}

// one-time: W^T split images, plain [n][k] bf16 rows
__global__ void k_wprep(const float* __restrict__ W) {
    int n = threadIdx.x;                       // 128 threads
    __nv_bfloat16* hi = (__nv_bfloat16*)g_whi;
    __nv_bfloat16* lo = (__nv_bfloat16*)g_wlo;
    for (int k = 0; k < D; k++) {
        float w = W[k * D + n];                // coalesced across threads
        float wh = bf16_hi(w);
        hi[n * D + k] = __float2bfloat16(w);
        lo[n * D + k] = __float2bfloat16(w - wh);
    }
}

// ============ mma.sync bf16 split GEMM: out = A@W^T via hi/lo ============
// CTA: 256 thr (8 warps), tile 128x128. Warp: 64 rows x 32 cols.
// smem: Ahi/Alo/Whi/Wlo, each [128 rows][128 bf16] in 256B rows with
// XOR-8 16B-chunk swizzle -> conflict-free ldmatrix.
#define GSM_BYTES (4 * 32768)

__device__ __forceinline__ void ldsm4(uint32_t* r, uint32_t addr) {
    asm volatile("ldmatrix.sync.aligned.m8n8.x4.shared.b16 {%0,%1,%2,%3}, [%4];"
                 : "=r"(r[0]), "=r"(r[1]), "=r"(r[2]), "=r"(r[3]) : "r"(addr));
}
__device__ __forceinline__ void mma16816(float* c, const uint32_t* a,
                                         uint32_t b0, uint32_t b1) {
    asm volatile(
        "mma.sync.aligned.m16n8k16.row.col.f32.bf16.bf16.f32 "
        "{%0,%1,%2,%3}, {%4,%5,%6,%7}, {%8,%9}, {%0,%1,%2,%3};"
        : "+f"(c[0]), "+f"(c[1]), "+f"(c[2]), "+f"(c[3])
        : "r"(a[0]), "r"(a[1]), "r"(a[2]), "r"(a[3]), "r"(b0), "r"(b1));
}

__global__ void __launch_bounds__(256, 1)
k_gemm_mma(const float* __restrict__ bias, float* __restrict__ out, int N) {
    extern __shared__ char sm[];
    char* A_hi = sm;
    char* A_lo = sm + 32768;
    char* W_hi = sm + 65536;
    char* W_lo = sm + 98304;
    int tid = threadIdx.x;
    int m0 = blockIdx.x * 128;

    // stage W (swizzled)
    for (int i = tid; i < 2048; i += 256) {
        int r = i >> 4, c = i & 15;
        int dst = r * 256 + ((c ^ (r & 7)) << 4);
        *(uint4*)(W_hi + dst) = g_whi[i];
        *(uint4*)(W_lo + dst) = g_wlo[i];
    }
    // stage A tile (swizzled, zero-pad tail rows)
    for (int i = tid; i < 2048; i += 256) {
        int r = i >> 4, c = i & 15;
        int gm = m0 + r;
        uint4 vh = make_uint4(0, 0, 0, 0), vl = vh;
        if (gm < N) { vh = g_ahi[(size_t)gm * 16 + c];
                      vl = g_alo[(size_t)gm * 16 + c]; }
        int dst = r * 256 + ((c ^ (r & 7)) << 4);
        *(uint4*)(A_hi + dst) = vh;
        *(uint4*)(A_lo + dst) = vl;
    }
    __syncthreads();

    int wid = tid >> 5, lane = tid & 31;
    int wm = wid & 1;        // 0/1 -> rows wm*64..+63
    int wn = wid >> 1;       // 0..3 -> cols wn*32..+31

    float acc[4][4][4];
    #pragma unroll
    for (int a = 0; a < 4; a++)
        #pragma unroll
        for (int b = 0; b < 4; b++)
            #pragma unroll
            for (int c = 0; c < 4; c++) acc[a][b][c] = 0.f;

    // ldmatrix lane addressing
    int a_row = (lane & 7) + ((lane >> 3) & 1) * 8;   // within m16 tile
    int a_co  = (lane >> 4);                           // k-chunk parity
    int b_row = (lane & 7) + (lane >> 4) * 8;          // within n16 tile
    int b_co  = ((lane >> 3) & 1);

    const char* Ab[3] = {A_hi, A_hi, A_lo};
    const char* Bb[3] = {W_hi, W_lo, W_hi};

    #pragma unroll
    for (int p = 0; p < 3; p++) {
        uint32_t abase = smem_u32(Ab[p]);
        uint32_t bbase = smem_u32(Bb[p]);
        #pragma unroll
        for (int kc = 0; kc < 8; kc++) {
            uint32_t af[4][4];
            #pragma unroll
            for (int mf = 0; mf < 4; mf++) {
                int row = wm * 64 + mf * 16 + a_row;
                int ch = 2 * kc + a_co;
                ldsm4(af[mf], abase + row * 256 + ((ch ^ (row & 7)) << 4));
            }
            uint32_t bf[2][4];
            #pragma unroll
            for (int nb = 0; nb < 2; nb++) {
                int row = wn * 32 + nb * 16 + b_row;
                int ch = 2 * kc + b_co;
                ldsm4(bf[nb], bbase + row * 256 + ((ch ^ (row & 7)) << 4));
            }
            #pragma unroll
            for (int mf = 0; mf < 4; mf++)
                #pragma unroll
                for (int n = 0; n < 4; n++)
                    mma16816(acc[mf][n], af[mf],
                             bf[n >> 1][(n & 1) * 2], bf[n >> 1][(n & 1) * 2 + 1]);
        }
    }

    // epilogue: fragment -> global float2 stores + bias
    int g = lane >> 2, tg = lane & 3;
    float2 bv[4];
    #pragma unroll
    for (int n = 0; n < 4; n++) {
        int col = wn * 32 + n * 8 + tg * 2;
        bv[n].x = __ldg(&bias[col]);
        bv[n].y = __ldg(&bias[col + 1]);
    }
    #pragma unroll
    for (int mf = 0; mf < 4; mf++) {
        int row0 = m0 + wm * 64 + mf * 16 + g;
        #pragma unroll
        for (int n = 0; n < 4; n++) {
            int col = wn * 32 + n * 8 + tg * 2;
            if (row0 < N) {
                float2 o = make_float2(acc[mf][n][0] + bv[n].x,
                                       acc[mf][n][1] + bv[n].y);
                *(float2*)(out + (size_t)row0 * D + col) = o;
            }
            if (row0 + 8 < N) {
                float2 o = make_float2(acc[mf][n][2] + bv[n].x,
                                       acc[mf][n][3] + bv[n].y);
                *(float2*)(out + (size_t)(row0 + 8) * D + col) = o;
            }
        }
    }
}

// ======================= launch =======================
extern "C" void kernel_launch(void* const* d_in, const int* in_sizes, int n_in,
                              void* d_out, int out_size) {
    const float* x      = (const float*)d_in[0];
    const int*   ep     = (const int*)d_in[1];
    const float* att_l  = (const float*)d_in[2];
    const float* att_r  = (const float*)d_in[3];
    const float* weight = (const float*)d_in[4];
    const float* bias   = (const float*)d_in[5];
    float*       out    = (float*)d_out;

    int N = in_sizes[0] / D;
    int E = in_sizes[1] / 2;
    int Ep = E < 65536 ? E : 65536;

    const float4* x4 = (const float4*)x;

    k_zero<<<(N + 255) / 256, 256>>>(N);
    k_probe<<<16, 256>>>((const unsigned int*)ep, Ep);
    k_setflag<<<1, 1>>>();
    k_count<<<(E + 255) / 256, 256>>>(ep, E);
    k_node<<<(N * 32 + 255) / 256, 256>>>(x4, (const float4*)att_l,
                                          (const float4*)att_r, N);
    k_scan<<<1, 1024>>>(N);
    k_build<<<(E + 255) / 256, 256>>>(ep, E);
    k_gather<<<(N * 32 + 255) / 256, 256>>>(x4, N);
    k_wprep<<<1, 128>>>(weight);
    cudaFuncSetAttribute(k_gemm_mma, cudaFuncAttributeMaxDynamicSharedMemorySize,
                         GSM_BYTES);
    k_gemm_mma<<<(N + 127) / 128, 256, GSM_BYTES>>>(bias, out, N);
}

// round 8
// speedup vs baseline: 1.3371x; 1.3371x over previous
#include <cuda_runtime.h>
#include <cuda_bf16.h>
#include <cstdint>

#define D 128
#define MAXN 65536
#define MAXE (1 << 20)
#define EPS 0.1f

// ======================= scratch (device globals) =======================
__device__ int          g_is64;
__device__ unsigned int g_or;
__device__ int   g_cnt[MAXN];
__device__ int   g_cursor[MAXN];
__device__ int   g_off[MAXN + 1];
__device__ int   g_csr[MAXE];
__device__ float g_coef[MAXE];
__device__ float g_al[MAXN];
__device__ float g_ar[MAXN];
__device__ float g_dinv[MAXN];
// bf16 split of aggregated features, row-major [MAXN][128] bf16 = 16 uint4/row
__device__ uint4 g_ahi[(size_t)MAXN * 16];
__device__ uint4 g_alo[(size_t)MAXN * 16];
// W^T split, row-major [n][k] bf16 (k contiguous), 16 uint4 per row
__device__ uint4 g_whi[2048];
__device__ uint4 g_wlo[2048];

__device__ __forceinline__ uint32_t smem_u32(const void* p) {
    uint32_t a;
    asm("{.reg .u64 t; cvta.to.shared.u64 t, %1; cvt.u32.u64 %0, t;}"
        : "=r"(a) : "l"(p));
    return a;
}
__device__ __forceinline__ uint32_t pack_bf16x2(float a, float b) {
    __nv_bfloat16 ha = __float2bfloat16(a), hb = __float2bfloat16(b);
    return ((uint32_t)*(uint16_t*)&hb << 16) | *(uint16_t*)&ha;
}
__device__ __forceinline__ float bf16_hi(float a) {
    return __bfloat162float(__float2bfloat16(a));
}

// ======================= preprocessing kernels =======================
__global__ void k_zero(int N) {
    int i = blockIdx.x * blockDim.x + threadIdx.x;
    if (i < N) { g_cnt[i] = 0; g_cursor[i] = 0; }
    if (i == 0) g_or = 0u;
}
// probe: OR odd int32 words of first Ep pairs (int64 -> all hi-words == 0)
__global__ void k_probe(const unsigned int* __restrict__ p, int Ep) {
    unsigned int v = 0;
    for (int i = blockIdx.x * blockDim.x + threadIdx.x; i < Ep;
         i += gridDim.x * blockDim.x)
        v |= p[2 * i + 1];
    #pragma unroll
    for (int o = 16; o > 0; o >>= 1) v |= __shfl_down_sync(0xFFFFFFFFu, v, o);
    if ((threadIdx.x & 31) == 0 && v) atomicOr(&g_or, v);
}
__global__ void k_setflag() { g_is64 = (g_or == 0u) ? 1 : 0; }

__device__ __forceinline__ int edge_src(const int* __restrict__ p, int E, int i) {
    return g_is64 ? p[2 * i] : p[i];
}
__device__ __forceinline__ int edge_dst(const int* __restrict__ p, int E, int i) {
    return g_is64 ? p[2 * (E + i)] : p[E + i];
}

// count in-degree: 4 edges per thread, loads batched for MLP
__global__ void k_count(const int* __restrict__ p, int E) {
    int base = (blockIdx.x * blockDim.x + threadIdx.x) * 4;
    if (base + 3 < E) {
        int c0 = edge_dst(p, E, base + 0);
        int c1 = edge_dst(p, E, base + 1);
        int c2 = edge_dst(p, E, base + 2);
        int c3 = edge_dst(p, E, base + 3);
        atomicAdd(&g_cnt[c0], 1);
        atomicAdd(&g_cnt[c1], 1);
        atomicAdd(&g_cnt[c2], 1);
        atomicAdd(&g_cnt[c3], 1);
    } else {
        for (int i = base; i < E; i++)
            atomicAdd(&g_cnt[edge_dst(p, E, i)], 1);
    }
}

__global__ void k_node(const float4* __restrict__ x4,
                       const float4* __restrict__ attl4,
                       const float4* __restrict__ attr4, int N) {
    int warp = (blockIdx.x * blockDim.x + threadIdx.x) >> 5;
    int lane = threadIdx.x & 31;
    if (warp >= N) return;
    float4 xv = x4[(size_t)warp * 32 + lane];
    float4 lv = attl4[lane];
    float4 rv = attr4[lane];
    float pl = xv.x * lv.x + xv.y * lv.y + xv.z * lv.z + xv.w * lv.w;
    float pr = xv.x * rv.x + xv.y * rv.y + xv.z * rv.z + xv.w * rv.w;
    #pragma unroll
    for (int o = 16; o > 0; o >>= 1) {
        pl += __shfl_down_sync(0xFFFFFFFFu, pl, o);
        pr += __shfl_down_sync(0xFFFFFFFFu, pr, o);
    }
    if (lane == 0) {
        g_al[warp] = pl;
        g_ar[warp] = pr;
        g_dinv[warp] = rsqrtf((float)g_cnt[warp] + 1.0f);
    }
}

__global__ void k_scan(int N) {
    __shared__ int warp_sums[32];
    int t = threadIdx.x;
    int lane = t & 31, w = t >> 5;
    int chunk = (N + 1023) >> 10;
    int begin = t * chunk;
    int end = begin + chunk; if (end > N) end = N; if (begin > N) begin = N;
    int local = 0;
    for (int i = begin; i < end; i++) local += g_cnt[i];
    int v = local;
    #pragma unroll
    for (int o = 1; o < 32; o <<= 1) {
        int u = __shfl_up_sync(0xFFFFFFFFu, v, o);
        if (lane >= o) v += u;
    }
    if (lane == 31) warp_sums[w] = v;
    __syncthreads();
    if (w == 0) {
        int s = warp_sums[lane];
        #pragma unroll
        for (int o = 1; o < 32; o <<= 1) {
            int u = __shfl_up_sync(0xFFFFFFFFu, s, o);
            if (lane >= o) s += u;
        }
        warp_sums[lane] = s;
    }
    __syncthreads();
    int incl = v + (w > 0 ? warp_sums[w - 1] : 0);
    int run = incl - local;
    for (int i = begin; i < end; i++) { g_off[i] = run; run += g_cnt[i]; }
    if (t == 1023) g_off[N] = run;
}

// CSR build + per-edge coefficient (tanh once per edge)
__global__ void k_build(const int* __restrict__ p, int E) {
    int i = blockIdx.x * blockDim.x + threadIdx.x;
    if (i < E) {
        int r = edge_src(p, E, i);
        int c = edge_dst(p, E, i);
        int pos = g_off[c] + atomicAdd(&g_cursor[c], 1);
        g_csr[pos] = r;
        g_coef[pos] = tanhf(g_al[r] + g_ar[c]) * g_dinv[r] * g_dinv[c];
    }
}

// gather-aggregate (warp/node, register acc) -> bf16 hi/lo split output
__global__ void k_gather(const float4* __restrict__ x4, int N) {
    int n = (blockIdx.x * blockDim.x + threadIdx.x) >> 5;
    int lane = threadIdx.x & 31;
    if (n >= N) return;
    float dv  = g_dinv[n];
    float s = EPS + tanhf(g_al[n] + g_ar[n]) * dv * dv;   // self loop + eps
    float4 xv = x4[(size_t)n * 32 + lane];
    float4 acc = make_float4(xv.x * s, xv.y * s, xv.z * s, xv.w * s);
    int e   = g_off[n];
    int end = g_off[n + 1];
    for (; e < end; e++) {
        int r = g_csr[e];
        float coef = g_coef[e];
        float4 v = x4[(size_t)r * 32 + lane];
        acc.x += v.x * coef; acc.y += v.y * coef;
        acc.z += v.z * coef; acc.w += v.w * coef;
    }
    float hx = bf16_hi(acc.x), hy = bf16_hi(acc.y);
    float hz = bf16_hi(acc.z), hw = bf16_hi(acc.w);
    uint2 hi = make_uint2(pack_bf16x2(acc.x, acc.y), pack_bf16x2(acc.z, acc.w));
    uint2 lo = make_uint2(pack_bf16x2(acc.x - hx, acc.y - hy),
                          pack_bf16x2(acc.z - hz, acc.w - hw));
    ((uint2*)g_ahi)[(size_t)n * 32 + lane] = hi;
    ((uint2*)g_alo)[(size_t)n * 32 + lane] = lo;
}

// one-time: W^T split images, [n][k] bf16 rows. 128 blocks x 128 threads:
// block n writes row n contiguously (coalesced); reads have high cross-block MLP.
__global__ void k_wprep(const float* __restrict__ W) {
    int n = blockIdx.x;
    int k = threadIdx.x;
    float w = __ldg(&W[k * D + n]);
    float wh = bf16_hi(w);
    ((__nv_bfloat16*)g_whi)[n * D + k] = __float2bfloat16(w);
    ((__nv_bfloat16*)g_wlo)[n * D + k] = __float2bfloat16(w - wh);
}

// ============ mma.sync bf16 split GEMM: out = A@W^T via hi/lo ============
#define GSM_BYTES (4 * 32768)

__device__ __forceinline__ void ldsm4(uint32_t* r, uint32_t addr) {
    asm volatile("ldmatrix.sync.aligned.m8n8.x4.shared.b16 {%0,%1,%2,%3}, [%4];"
                 : "=r"(r[0]), "=r"(r[1]), "=r"(r[2]), "=r"(r[3]) : "r"(addr));
}
__device__ __forceinline__ void mma16816(float* c, const uint32_t* a,
                                         uint32_t b0, uint32_t b1) {
    asm volatile(
        "mma.sync.aligned.m16n8k16.row.col.f32.bf16.bf16.f32 "
        "{%0,%1,%2,%3}, {%4,%5,%6,%7}, {%8,%9}, {%0,%1,%2,%3};"
        : "+f"(c[0]), "+f"(c[1]), "+f"(c[2]), "+f"(c[3])
        : "r"(a[0]), "r"(a[1]), "r"(a[2]), "r"(a[3]), "r"(b0), "r"(b1));
}

__global__ void __launch_bounds__(256, 1)
k_gemm_mma(const float* __restrict__ bias, float* __restrict__ out, int N) {
    extern __shared__ char sm[];
    char* A_hi = sm;
    char* A_lo = sm + 32768;
    char* W_hi = sm + 65536;
    char* W_lo = sm + 98304;
    int tid = threadIdx.x;
    int m0 = blockIdx.x * 128;

    // stage W (swizzled)
    for (int i = tid; i < 2048; i += 256) {
        int r = i >> 4, c = i & 15;
        int dst = r * 256 + ((c ^ (r & 7)) << 4);
        *(uint4*)(W_hi + dst) = g_whi[i];
        *(uint4*)(W_lo + dst) = g_wlo[i];
    }
    // stage A tile (swizzled, zero-pad tail rows)
    for (int i = tid; i < 2048; i += 256) {
        int r = i >> 4, c = i & 15;
        int gm = m0 + r;
        uint4 vh = make_uint4(0, 0, 0, 0), vl = vh;
        if (gm < N) { vh = g_ahi[(size_t)gm * 16 + c];
                      vl = g_alo[(size_t)gm * 16 + c]; }
        int dst = r * 256 + ((c ^ (r & 7)) << 4);
        *(uint4*)(A_hi + dst) = vh;
        *(uint4*)(A_lo + dst) = vl;
    }
    __syncthreads();

    int wid = tid >> 5, lane = tid & 31;
    int wm = wid & 1;        // 0/1 -> rows wm*64..+63
    int wn = wid >> 1;       // 0..3 -> cols wn*32..+31

    float acc[4][4][4];
    #pragma unroll
    for (int a = 0; a < 4; a++)
        #pragma unroll
        for (int b = 0; b < 4; b++)
            #pragma unroll
            for (int c = 0; c < 4; c++) acc[a][b][c] = 0.f;

    int a_row = (lane & 7) + ((lane >> 3) & 1) * 8;
    int a_co  = (lane >> 4);
    int b_row = (lane & 7) + (lane >> 4) * 8;
    int b_co  = ((lane >> 3) & 1);

    const char* Ab[3] = {A_hi, A_hi, A_lo};
    const char* Bb[3] = {W_hi, W_lo, W_hi};

    #pragma unroll
    for (int p = 0; p < 3; p++) {
        uint32_t abase = smem_u32(Ab[p]);
        uint32_t bbase = smem_u32(Bb[p]);
        #pragma unroll
        for (int kc = 0; kc < 8; kc++) {
            uint32_t af[4][4];
            #pragma unroll
            for (int mf = 0; mf < 4; mf++) {
                int row = wm * 64 + mf * 16 + a_row;
                int ch = 2 * kc + a_co;
                ldsm4(af[mf], abase + row * 256 + ((ch ^ (row & 7)) << 4));
            }
            uint32_t bf[2][4];
            #pragma unroll
            for (int nb = 0; nb < 2; nb++) {
                int row = wn * 32 + nb * 16 + b_row;
                int ch = 2 * kc + b_co;
                ldsm4(bf[nb], bbase + row * 256 + ((ch ^ (row & 7)) << 4));
            }
            #pragma unroll
            for (int mf = 0; mf < 4; mf++)
                #pragma unroll
                for (int n = 0; n < 4; n++)
                    mma16816(acc[mf][n], af[mf],
                             bf[n >> 1][(n & 1) * 2], bf[n >> 1][(n & 1) * 2 + 1]);
        }
    }

    // epilogue: fragment -> global float2 stores + bias
    int g = lane >> 2, tg = lane & 3;
    float2 bv[4];
    #pragma unroll
    for (int n = 0; n < 4; n++) {
        int col = wn * 32 + n * 8 + tg * 2;
        bv[n].x = __ldg(&bias[col]);
        bv[n].y = __ldg(&bias[col + 1]);
    }
    #pragma unroll
    for (int mf = 0; mf < 4; mf++) {
        int row0 = m0 + wm * 64 + mf * 16 + g;
        #pragma unroll
        for (int n = 0; n < 4; n++) {
            int col = wn * 32 + n * 8 + tg * 2;
            if (row0 < N) {
                float2 o = make_float2(acc[mf][n][0] + bv[n].x,
                                       acc[mf][n][1] + bv[n].y);
                *(float2*)(out + (size_t)row0 * D + col) = o;
            }
            if (row0 + 8 < N) {
                float2 o = make_float2(acc[mf][n][2] + bv[n].x,
                                       acc[mf][n][3] + bv[n].y);
                *(float2*)(out + (size_t)(row0 + 8) * D + col) = o;
            }
        }
    }
}

// ======================= launch =======================
extern "C" void kernel_launch(void* const* d_in, const int* in_sizes, int n_in,
                              void* d_out, int out_size) {
    const float* x      = (const float*)d_in[0];
    const int*   ep     = (const int*)d_in[1];
    const float* att_l  = (const float*)d_in[2];
    const float* att_r  = (const float*)d_in[3];
    const float* weight = (const float*)d_in[4];
    const float* bias   = (const float*)d_in[5];
    float*       out    = (float*)d_out;

    int N = in_sizes[0] / D;
    int E = in_sizes[1] / 2;
    int Ep = E < 65536 ? E : 65536;

    const float4* x4 = (const float4*)x;

    k_zero<<<(N + 255) / 256, 256>>>(N);
    k_probe<<<16, 256>>>((const unsigned int*)ep, Ep);
    k_setflag<<<1, 1>>>();
    k_count<<<(E / 4 + 255) / 256, 256>>>(ep, E);
    k_node<<<(N * 32 + 255) / 256, 256>>>(x4, (const float4*)att_l,
                                          (const float4*)att_r, N);
    k_scan<<<1, 1024>>>(N);
    k_build<<<(E + 255) / 256, 256>>>(ep, E);
    k_gather<<<(N * 32 + 255) / 256, 256>>>(x4, N);
    k_wprep<<<128, 128>>>(weight);
    cudaFuncSetAttribute(k_gemm_mma, cudaFuncAttributeMaxDynamicSharedMemorySize,
                         GSM_BYTES);
    k_gemm_mma<<<(N + 127) / 128, 256, GSM_BYTES>>>(bias, out, N);
}